// round 2
// baseline (speedup 1.0000x reference)
#include <cuda_runtime.h>
#include <math.h>

#define NS 128      // hidden states
#define DD 128      // observation dim
#define BB 16       // batch
#define TT 4096     // sequence length
#define LOG2PI_F 1.8378770664093453f

// ---- device scratch (no allocs allowed) ----
__device__ float g_W[NS * NS];       // softmax(transition) row-major: W[i][j]
__device__ float g_cA[NS * DD];      // -0.5 / var
__device__ float g_cB[NS * DD];      // mean / var
__device__ float g_k[NS];            // -0.5*(sum mu^2/var + sum log var + D*log2pi)
__device__ float g_logpi[NS];
__device__ float g_E[BB * TT * NS];  // emission logprobs [B][T][N]  (32 MB)
__device__ float g_partial[BB];      // per-batch log-likelihood

// ============================================================
// Setup: softmax(transition) -> W, log_softmax(priors), emission coefs
// ============================================================
__global__ void setup_kernel(const float* __restrict__ trans,
                             const float* __restrict__ priors,
                             const float* __restrict__ means,
                             const float* __restrict__ scales) {
    int n = threadIdx.x;  // 0..127
    __shared__ float spri[NS];
    spri[n] = priors[n];
    __syncthreads();

    // log_pi (computed redundantly per thread; setup cost irrelevant)
    float mx = -1e30f;
    for (int i = 0; i < NS; i++) mx = fmaxf(mx, spri[i]);
    float se = 0.f;
    for (int i = 0; i < NS; i++) se += expf(spri[i] - mx);
    g_logpi[n] = spri[n] - mx - logf(se);

    // W row n = softmax over j of transition[n][:]
    float rmx = -1e30f;
    for (int j = 0; j < NS; j++) rmx = fmaxf(rmx, trans[n * NS + j]);
    float rs = 0.f;
    for (int j = 0; j < NS; j++) rs += expf(trans[n * NS + j] - rmx);
    float inv_rs = 1.0f / rs;
    for (int j = 0; j < NS; j++)
        g_W[n * NS + j] = expf(trans[n * NS + j] - rmx) * inv_rs;

    // emission coefficients for state n
    float c = 0.f;
    for (int d = 0; d < DD; d++) {
        float x = scales[n * DD + d];
        // softplus(x) = log1p(exp(x)) (stable form for large x)
        float sp = (x > 20.f) ? x : log1pf(expf(x));
        float var = sp + 1e-6f;
        float inv = 1.0f / var;
        float mu = means[n * DD + d];
        g_cA[n * DD + d] = -0.5f * inv;
        g_cB[n * DD + d] = mu * inv;
        c += mu * mu * inv + logf(var);
    }
    g_k[n] = -0.5f * (c + (float)DD * LOG2PI_F);
}

// ============================================================
// Emission: E[b][t][n] = k_n + sum_d (x^2 * cA[n][d] + x * cB[n][d])
// block = 128 threads (thread = state n), covers TROWS time rows
// ============================================================
#define TROWS 16
__global__ __launch_bounds__(128) void emis_kernel(const float* __restrict__ X) {
    __shared__ float sX[TROWS * DD];
    __shared__ float sQ[TROWS * DD];
    int n = threadIdx.x;
    int blk = blockIdx.x;                 // 0 .. B*T/TROWS - 1
    int b = blk >> 8;                     // / (T/TROWS) = 256
    int tc = blk & 255;
    const float* Xp = X + ((size_t)b * TT + (size_t)tc * TROWS) * DD;

    for (int k = n; k < TROWS * DD; k += 128) {
        float x = Xp[k];
        sX[k] = x;
        sQ[k] = x * x;
    }
    __syncthreads();

    float acc[TROWS];
    float kn = g_k[n];
#pragma unroll
    for (int t = 0; t < TROWS; t++) acc[t] = kn;

    for (int dc = 0; dc < 4; dc++) {
        float cA[32], cB[32];
        const float4* a4 = (const float4*)(g_cA + n * DD + dc * 32);
        const float4* b4 = (const float4*)(g_cB + n * DD + dc * 32);
#pragma unroll
        for (int q = 0; q < 8; q++) {
            float4 va = a4[q], vb = b4[q];
            cA[4 * q + 0] = va.x; cA[4 * q + 1] = va.y;
            cA[4 * q + 2] = va.z; cA[4 * q + 3] = va.w;
            cB[4 * q + 0] = vb.x; cB[4 * q + 1] = vb.y;
            cB[4 * q + 2] = vb.z; cB[4 * q + 3] = vb.w;
        }
#pragma unroll
        for (int t = 0; t < TROWS; t++) {
            const float4* x4 = (const float4*)(sX + t * DD + dc * 32);
            const float4* q4 = (const float4*)(sQ + t * DD + dc * 32);
            float a0 = 0.f, a1 = 0.f;
#pragma unroll
            for (int q = 0; q < 8; q += 2) {
                float4 xv0 = x4[q],     qv0 = q4[q];
                float4 xv1 = x4[q + 1], qv1 = q4[q + 1];
                a0 = fmaf(qv0.x, cA[4 * q + 0], a0);
                a0 = fmaf(xv0.x, cB[4 * q + 0], a0);
                a0 = fmaf(qv0.y, cA[4 * q + 1], a0);
                a0 = fmaf(xv0.y, cB[4 * q + 1], a0);
                a0 = fmaf(qv0.z, cA[4 * q + 2], a0);
                a0 = fmaf(xv0.z, cB[4 * q + 2], a0);
                a0 = fmaf(qv0.w, cA[4 * q + 3], a0);
                a0 = fmaf(xv0.w, cB[4 * q + 3], a0);
                a1 = fmaf(qv1.x, cA[4 * q + 4], a1);
                a1 = fmaf(xv1.x, cB[4 * q + 4], a1);
                a1 = fmaf(qv1.y, cA[4 * q + 5], a1);
                a1 = fmaf(xv1.y, cB[4 * q + 5], a1);
                a1 = fmaf(qv1.z, cA[4 * q + 6], a1);
                a1 = fmaf(xv1.z, cB[4 * q + 6], a1);
                a1 = fmaf(qv1.w, cA[4 * q + 7], a1);
                a1 = fmaf(xv1.w, cB[4 * q + 7], a1);
            }
            acc[t] += a0 + a1;
        }
    }
    float* Eout = g_E + ((size_t)b * TT + (size_t)tc * TROWS) * NS;
#pragma unroll
    for (int t = 0; t < TROWS; t++) Eout[t * NS + n] = acc[t];
}

// ============================================================
// Forward recursion: 1 CTA per batch, 128 threads (thread = state j)
// W column resident in registers. Linear-domain matvec:
//   alpha'_j = e_j + m + log( sum_i exp(alpha_i - m) * W[i][j] )
// with per-warp normalization folded in via exp(wmax_w - m) scale factors.
// One __syncthreads per step (double-buffered p / wmax).
// ============================================================
__global__ __launch_bounds__(128, 1) void forward_kernel() {
    int b = blockIdx.x;
    int j = threadIdx.x;
    int w = j >> 5;
    int lane = j & 31;

    // W column j into registers
    float Wc[NS];
#pragma unroll
    for (int i = 0; i < NS; i++) Wc[i] = g_W[i * NS + j];

    __shared__ float sp[2][NS];
    __shared__ float swm[2][4];

    const float* Eb = g_E + (size_t)b * TT * NS;

    float alpha = g_logpi[j] + Eb[j];       // t = 0
    float eA = Eb[1 * NS + j];              // e for t = 1
    float eB = Eb[2 * NS + j];              // e for t = 2

    for (int t = 1; t < TT; ++t) {
        // prefetch e for t+2 (consumed 2 iterations later)
        int tp = (t + 2 < TT) ? (t + 2) : (TT - 1);
        float enew = __ldg(Eb + tp * NS + j);

        // per-warp max of alpha
        float wm = alpha;
        wm = fmaxf(wm, __shfl_xor_sync(0xffffffffu, wm, 16));
        wm = fmaxf(wm, __shfl_xor_sync(0xffffffffu, wm, 8));
        wm = fmaxf(wm, __shfl_xor_sync(0xffffffffu, wm, 4));
        wm = fmaxf(wm, __shfl_xor_sync(0xffffffffu, wm, 2));
        wm = fmaxf(wm, __shfl_xor_sync(0xffffffffu, wm, 1));

        float p = __expf(alpha - wm);       // in (0,1], per-warp normalized
        int pb = t & 1;
        sp[pb][j] = p;
        if (lane == 0) swm[pb][w] = wm;
        __syncthreads();

        float m01 = fmaxf(swm[pb][0], swm[pb][1]);
        float m23 = fmaxf(swm[pb][2], swm[pb][3]);
        float m = fmaxf(m01, m23);

        // matvec: s = sum_w exp(wmax_w - m) * sum_{i in warp w} p_i * W[i][j]
        float s = 0.f;
        const float4* p4 = (const float4*)sp[pb];
#pragma unroll
        for (int wg = 0; wg < 4; ++wg) {
            float a0 = 0.f, a1 = 0.f;
#pragma unroll
            for (int q = 0; q < 8; q += 2) {
                float4 v0 = p4[wg * 8 + q];
                float4 v1 = p4[wg * 8 + q + 1];
                a0 = fmaf(v0.x, Wc[wg * 32 + 4 * q + 0], a0);
                a0 = fmaf(v0.y, Wc[wg * 32 + 4 * q + 1], a0);
                a0 = fmaf(v0.z, Wc[wg * 32 + 4 * q + 2], a0);
                a0 = fmaf(v0.w, Wc[wg * 32 + 4 * q + 3], a0);
                a1 = fmaf(v1.x, Wc[wg * 32 + 4 * q + 4], a1);
                a1 = fmaf(v1.y, Wc[wg * 32 + 4 * q + 5], a1);
                a1 = fmaf(v1.z, Wc[wg * 32 + 4 * q + 6], a1);
                a1 = fmaf(v1.w, Wc[wg * 32 + 4 * q + 7], a1);
            }
            float f = __expf(swm[pb][wg] - m);
            s = fmaf(f, a0 + a1, s);
        }

        alpha = eA + m + __logf(s);
        eA = eB;
        eB = enew;
        // no second barrier needed: double-buffered sp/swm; a warp can only
        // reach iteration t+2's stores after everyone passed t+1's barrier,
        // which implies everyone finished reading buffer (t&1).
    }

    // final logsumexp over alpha (per batch)
    __syncthreads();   // make buffers reusable
    float wm = alpha;
    wm = fmaxf(wm, __shfl_xor_sync(0xffffffffu, wm, 16));
    wm = fmaxf(wm, __shfl_xor_sync(0xffffffffu, wm, 8));
    wm = fmaxf(wm, __shfl_xor_sync(0xffffffffu, wm, 4));
    wm = fmaxf(wm, __shfl_xor_sync(0xffffffffu, wm, 2));
    wm = fmaxf(wm, __shfl_xor_sync(0xffffffffu, wm, 1));
    if (lane == 0) swm[0][w] = wm;
    __syncthreads();
    float m = fmaxf(fmaxf(swm[0][0], swm[0][1]), fmaxf(swm[0][2], swm[0][3]));
    float p = __expf(alpha - m);
    p += __shfl_xor_sync(0xffffffffu, p, 16);
    p += __shfl_xor_sync(0xffffffffu, p, 8);
    p += __shfl_xor_sync(0xffffffffu, p, 4);
    p += __shfl_xor_sync(0xffffffffu, p, 2);
    p += __shfl_xor_sync(0xffffffffu, p, 1);
    if (lane == 0) sp[0][w] = p;
    __syncthreads();
    if (j == 0) {
        float s = sp[0][0] + sp[0][1] + sp[0][2] + sp[0][3];
        g_partial[b] = m + __logf(s);
    }
}

// deterministic fixed-order final sum
__global__ void final_kernel(float* __restrict__ out) {
    if (threadIdx.x == 0) {
        float s = 0.f;
        for (int b = 0; b < BB; b++) s += g_partial[b];
        out[0] = s;
    }
}

// ============================================================
extern "C" void kernel_launch(void* const* d_in, const int* in_sizes, int n_in,
                              void* d_out, int out_size) {
    const float* X      = (const float*)d_in[0];  // [B,T,D]
    const float* trans  = (const float*)d_in[1];  // [N,N]
    const float* priors = (const float*)d_in[2];  // [N]
    const float* means  = (const float*)d_in[3];  // [N,D]
    const float* scales = (const float*)d_in[4];  // [N,D]
    float* out = (float*)d_out;

    setup_kernel<<<1, 128>>>(trans, priors, means, scales);
    emis_kernel<<<(BB * TT) / TROWS, 128>>>(X);
    forward_kernel<<<BB, 128>>>();
    final_kernel<<<1, 32>>>(out);
}